// round 6
// baseline (speedup 1.0000x reference)
#include <cuda_runtime.h>
#include <cuda.h>
#include <cuda_fp16.h>
#include <cstdint>

// ================= problem dims =================
#define P_DIM 2048
#define Q_DIM 2048
#define NBATCH 16
#define T_DIM 256
#define K_HALF (NBATCH * T_DIM)   // 4096
#define K_TOT  (2 * K_HALF)       // 8192

// ================= gemm config =================
#define TILE_M 128
#define TILE_N 128
#define CHUNK_K 64                  // halves per k-chunk = 128 bytes per row
#define NCHUNK (K_TOT / CHUNK_K)    // 128
#define NSTAGE 3
#define A_TILE_BYTES (TILE_M * 128) // 16384
#define B_TILE_BYTES (TILE_N * 128) // 16384
#define STAGE_BYTES (A_TILE_BYTES + B_TILE_BYTES)   // 32768
#define SMEM_DATA0 1024
#define SMEM_DYN_BYTES (SMEM_DATA0 + NSTAGE * STAGE_BYTES)  // 99328

// trace constants: exp(-0.001/0.02), exp(-0.001/0.101)
#define DECAY_PM 0.95122942450071400f
#define DECAY_X  0.99014786313283800f
#define A_TRIPLET 0.0065f

#define NTRACE_BLK 256   // traces grid size == number of spike-count partials

// ============ static device scratch (no allocs allowed) ============
__device__ __half g_A[(size_t)P_DIM * K_TOT];   // [P, 8192]: [x_pre | pre]
__device__ __half g_B[(size_t)Q_DIM * K_TOT];   // [Q, 8192]: [post*(Ap+c*xt) | -Am*x_post]
__device__ unsigned int g_count_part[NTRACE_BLK];  // per-block spike counts (overwrite -> idempotent)

// ============ helpers ============
__device__ __forceinline__ uint32_t smem_u32(const void* p) {
    uint32_t a;
    asm("{ .reg .u64 t; cvta.to.shared.u64 t, %1; cvt.u32.u64 %0, t; }" : "=r"(a) : "l"(p));
    return a;
}
__device__ __forceinline__ uint32_t pack_h2(float lo, float hi) {
    __half2 h = __floats2half2_rn(lo, hi);
    return *reinterpret_cast<uint32_t*>(&h);
}

// ================= kernel 1: traces + operand packing =================
// 256 blocks x 256 threads; each thread owns one (b, n) sequence (recurrence serial in t).
__global__ void __launch_bounds__(256) traces_kernel(
    const float* __restrict__ pre,
    const float* __restrict__ post,
    const float* __restrict__ apP,
    const float* __restrict__ amP)
{
    __shared__ unsigned s_cnt[8];
    int idx = blockIdx.x * blockDim.x + threadIdx.x;   // 0..65535
    bool is_pre = idx < (NBATCH * P_DIM);
    int li = is_pre ? idx : idx - NBATCH * P_DIM;
    int n = li & (P_DIM - 1);
    int b = li >> 11;
    const float4* in4 = (const float4*)((is_pre ? pre : post) + ((size_t)(b * P_DIM + n) << 8));
    __half* o1 = (is_pre ? g_A : g_B) + (size_t)n * K_TOT + b * T_DIM;
    __half* o2 = o1 + K_HALF;
    unsigned cnt = 0;

    if (is_pre) {
        float x = 0.f;
        #pragma unroll 4
        for (int t8 = 0; t8 < T_DIM / 8; t8++) {
            float4 f0 = in4[2 * t8], f1 = in4[2 * t8 + 1];
            float fv[8] = {f0.x, f0.y, f0.z, f0.w, f1.x, f1.y, f1.z, f1.w};
            float xa[8];
            #pragma unroll
            for (int i = 0; i < 8; i++) {
                float s = fv[i];
                xa[i] = x;
                cnt += (s > 0.5f) ? 1u : 0u;
                x = DECAY_PM * (x + s);
            }
            uint4 ua, ub;
            ua.x = pack_h2(xa[0], xa[1]); ua.y = pack_h2(xa[2], xa[3]);
            ua.z = pack_h2(xa[4], xa[5]); ua.w = pack_h2(xa[6], xa[7]);
            ub.x = pack_h2(fv[0], fv[1]); ub.y = pack_h2(fv[2], fv[3]);
            ub.z = pack_h2(fv[4], fv[5]); ub.w = pack_h2(fv[6], fv[7]);
            *(uint4*)(o1 + t8 * 8) = ua;      // x_pre trace
            *(uint4*)(o2 + t8 * 8) = ub;      // raw pre spikes (exact in fp16)
        }
    } else {
        float Ap = *apP;
        float Am = *amP;
        float xm = 0.f, xt = 0.f;
        #pragma unroll 4
        for (int t8 = 0; t8 < T_DIM / 8; t8++) {
            float4 f0 = in4[2 * t8], f1 = in4[2 * t8 + 1];
            float fv[8] = {f0.x, f0.y, f0.z, f0.w, f1.x, f1.y, f1.z, f1.w};
            float v1[8], v2[8];
            #pragma unroll
            for (int i = 0; i < 8; i++) {
                float s = fv[i];
                v1[i] = s * (Ap + A_TRIPLET * xt);   // ltp + triplet coefficient
                v2[i] = -Am * xm;                    // -ltd coefficient
                cnt += (s > 0.5f) ? 1u : 0u;
                xm = DECAY_PM * (xm + s);
                xt = DECAY_X * (xt + s);
            }
            uint4 ua, ub;
            ua.x = pack_h2(v1[0], v1[1]); ua.y = pack_h2(v1[2], v1[3]);
            ua.z = pack_h2(v1[4], v1[5]); ua.w = pack_h2(v1[6], v1[7]);
            ub.x = pack_h2(v2[0], v2[1]); ub.y = pack_h2(v2[2], v2[3]);
            ub.z = pack_h2(v2[4], v2[5]); ub.w = pack_h2(v2[6], v2[7]);
            *(uint4*)(o1 + t8 * 8) = ua;
            *(uint4*)(o2 + t8 * 8) = ub;
        }
    }
    // deterministic spike-count: warp reduce -> block reduce -> overwrite partial slot
    #pragma unroll
    for (int o = 16; o; o >>= 1) cnt += __shfl_xor_sync(0xffffffffu, cnt, o);
    if ((threadIdx.x & 31) == 0) s_cnt[threadIdx.x >> 5] = cnt;
    __syncthreads();
    if (threadIdx.x == 0) {
        unsigned t = 0;
        #pragma unroll
        for (int i = 0; i < 8; i++) t += s_cnt[i];
        g_count_part[blockIdx.x] = t;   // overwrite: idempotent across graph replays
    }
}

// ================= mma.sync building blocks (sm_80-compatible PTX) =============
__device__ __forceinline__ void ldsm4(uint32_t& r0, uint32_t& r1, uint32_t& r2, uint32_t& r3,
                                      uint32_t addr) {
    asm volatile("ldmatrix.sync.aligned.m8n8.x4.shared.b16 {%0,%1,%2,%3}, [%4];"
                 : "=r"(r0), "=r"(r1), "=r"(r2), "=r"(r3) : "r"(addr));
}
__device__ __forceinline__ void mma16816(float* d, const uint32_t* a, uint32_t b0, uint32_t b1) {
    asm volatile(
        "mma.sync.aligned.m16n8k16.row.col.f32.f16.f16.f32 "
        "{%0,%1,%2,%3}, {%4,%5,%6,%7}, {%8,%9}, {%0,%1,%2,%3};"
        : "+f"(d[0]), "+f"(d[1]), "+f"(d[2]), "+f"(d[3])
        : "r"(a[0]), "r"(a[1]), "r"(a[2]), "r"(a[3]), "r"(b0), "r"(b1));
}
__device__ __forceinline__ void cpasync16(uint32_t dst, const void* src) {
    asm volatile("cp.async.cg.shared.global [%0], [%1], 16;" :: "r"(dst), "l"(src));
}

// ================= kernel 2: GEMM + fused epilogue =================
// grid (16,16) = 256 CTAs, 256 threads (8 warps, warp grid 2x4, warp tile 64x32).
// D[p,q] = A[p,:].B[q,:]^T over K=8192;  out = clip(weights + D * scale, -2, 2)
__global__ void __launch_bounds__(256, 2) stdp_gemm_kernel(
    const float* __restrict__ weights,
    float* __restrict__ out)
{
    extern __shared__ __align__(1024) char smem[];
    uint32_t sb = smem_u32(smem);
    int tid = threadIdx.x;
    int wid = tid >> 5, lane = tid & 31;
    int m0 = blockIdx.x * TILE_M;
    int q0 = blockIdx.y * TILE_N;

    int wm = (wid & 1) * 64;        // warp M offset (2 row-groups of 64)
    int wn = (wid >> 1) * 32;       // warp N offset (4 col-groups of 32)
    const __half* Ag = g_A;
    const __half* Bg = g_B;

    float acc[64];
    #pragma unroll
    for (int i = 0; i < 64; i++) acc[i] = 0.f;

    // stage loader: 256 threads x 16B, 4 iters per operand
    auto load_stage = [&](int s, int kbase) {
        uint32_t a_s = sb + SMEM_DATA0 + s * STAGE_BYTES;
        uint32_t b_s = a_s + A_TILE_BYTES;
        #pragma unroll
        for (int i = 0; i < 4; i++) {
            int id = i * 256 + tid;            // 0..1023
            int row = id >> 3, ch = id & 7;
            uint32_t so = (uint32_t)(row * 128 + ((ch ^ (row & 7)) << 4));
            cpasync16(a_s + so, Ag + (size_t)(m0 + row) * K_TOT + kbase + ch * 8);
            cpasync16(b_s + so, Bg + (size_t)(q0 + row) * K_TOT + kbase + ch * 8);
        }
    };

    load_stage(0, 0);
    asm volatile("cp.async.commit_group;" ::: "memory");
    load_stage(1, CHUNK_K);
    asm volatile("cp.async.commit_group;" ::: "memory");

    int s_cur = 0, s_nxt = 2;
    #pragma unroll 1
    for (int c = 0; c < NCHUNK; c++) {
        asm volatile("cp.async.wait_group 1;" ::: "memory");
        __syncthreads();
        if (c + 2 < NCHUNK) load_stage(s_nxt, (c + 2) * CHUNK_K);
        asm volatile("cp.async.commit_group;" ::: "memory");

        uint32_t a_s = sb + SMEM_DATA0 + s_cur * STAGE_BYTES;
        uint32_t b_s = a_s + A_TILE_BYTES;
        #pragma unroll
        for (int kk = 0; kk < 4; kk++) {
            uint32_t af[4][4], bf[2][4];
            #pragma unroll
            for (int mt = 0; mt < 4; mt++) {
                int m_r = wm + mt * 16 + (lane & 15);
                int kch = kk * 2 + (lane >> 4);
                ldsm4(af[mt][0], af[mt][1], af[mt][2], af[mt][3],
                      a_s + (uint32_t)(m_r * 128 + ((kch ^ (m_r & 7)) << 4)));
            }
            #pragma unroll
            for (int pr = 0; pr < 2; pr++) {
                int g = lane >> 3;
                int n_r = wn + pr * 16 + (lane & 7) + (g >> 1) * 8;
                int kch = kk * 2 + (g & 1);
                ldsm4(bf[pr][0], bf[pr][1], bf[pr][2], bf[pr][3],
                      b_s + (uint32_t)(n_r * 128 + ((kch ^ (n_r & 7)) << 4)));
            }
            #pragma unroll
            for (int mt = 0; mt < 4; mt++) {
                #pragma unroll
                for (int nt = 0; nt < 4; nt++) {
                    int pr = nt >> 1, off = (nt & 1) * 2;
                    mma16816(&acc[(mt * 4 + nt) * 4], af[mt], bf[pr][off], bf[pr][off + 1]);
                }
            }
        }
        s_cur = (s_cur + 1 == NSTAGE) ? 0 : s_cur + 1;
        s_nxt = (s_nxt + 1 == NSTAGE) ? 0 : s_nxt + 1;
    }

    // ---- spike-count reduction (partials written by traces_kernel) ----
    unsigned c2 = g_count_part[tid];
    #pragma unroll
    for (int o = 16; o; o >>= 1) c2 += __shfl_xor_sync(0xffffffffu, c2, o);
    unsigned* sc = (unsigned*)(smem + 128);   // header region, never a cp.async target
    if (lane == 0) sc[wid] = c2;
    __syncthreads();
    unsigned ct = 0;
    #pragma unroll
    for (int i = 0; i < 8; i++) ct += sc[i];
    float act = (float)ct * (1.0f / (NBATCH * T_DIM));
    float scale = sqrtf(0.1f / (act + 1e-6f));

    // ---- fused epilogue ----
    #pragma unroll
    for (int mt = 0; mt < 4; mt++) {
        int r0 = m0 + wm + mt * 16 + (lane >> 2);
        #pragma unroll
        for (int nt = 0; nt < 4; nt++) {
            int cidx = q0 + wn + nt * 8 + (lane & 3) * 2;
            const float* d = &acc[(mt * 4 + nt) * 4];
            {
                const float2 w = *(const float2*)(weights + (size_t)r0 * Q_DIM + cidx);
                float2 o;
                o.x = fminf(fmaxf(fmaf(d[0], scale, w.x), -2.f), 2.f);
                o.y = fminf(fmaxf(fmaf(d[1], scale, w.y), -2.f), 2.f);
                *(float2*)(out + (size_t)r0 * Q_DIM + cidx) = o;
            }
            {
                const float2 w = *(const float2*)(weights + (size_t)(r0 + 8) * Q_DIM + cidx);
                float2 o;
                o.x = fminf(fmaxf(fmaf(d[2], scale, w.x), -2.f), 2.f);
                o.y = fminf(fmaxf(fmaf(d[3], scale, w.y), -2.f), 2.f);
                *(float2*)(out + (size_t)(r0 + 8) * Q_DIM + cidx) = o;
            }
        }
    }
}

// ================= host =================
extern "C" void kernel_launch(void* const* d_in, const int* in_sizes, int n_in,
                              void* d_out, int out_size)
{
    const float* pre  = (const float*)d_in[0];
    const float* post = (const float*)d_in[1];
    const float* w    = (const float*)d_in[2];
    const float* ap   = (const float*)d_in[3];
    const float* am   = (const float*)d_in[4];
    float* out = (float*)d_out;

    traces_kernel<<<NTRACE_BLK, 256>>>(pre, post, ap, am);

    cudaFuncSetAttribute(stdp_gemm_kernel, cudaFuncAttributeMaxDynamicSharedMemorySize,
                         SMEM_DYN_BYTES);
    dim3 grid(P_DIM / TILE_M, Q_DIM / TILE_N);   // (16, 16)
    stdp_gemm_kernel<<<grid, 256, SMEM_DYN_BYTES>>>(w, out);
}

// round 7
// speedup vs baseline: 2.5352x; 2.5352x over previous
#include <cuda_runtime.h>
#include <cuda.h>
#include <cuda_fp16.h>
#include <cstdint>

// ================= problem dims =================
#define P_DIM 2048
#define Q_DIM 2048
#define NBATCH 16
#define T_DIM 256
#define K_DATA 4096                 // (t,b) columns
#define K_EXTRA 4096                // start of boundary columns (16 of them)
#define K_COLS 4160                 // padded to 65 chunks of 64 (pad stays zero)

// ================= gemm config (R4-proven: 128 thr, warp grid 2x2) ==========
#define TILE_M 128
#define TILE_N 128
#define CHUNK_K 64                  // halves per k-chunk = 128 bytes per row
#define NCHUNK (K_COLS / CHUNK_K)   // 65
#define NSTAGE 3
#define A_TILE_BYTES (TILE_M * 128) // 16384
#define B_TILE_BYTES (TILE_N * 128) // 16384
#define STAGE_BYTES (A_TILE_BYTES + B_TILE_BYTES)   // 32768
#define SMEM_DATA0 1024
#define SMEM_DYN_BYTES (SMEM_DATA0 + NSTAGE * STAGE_BYTES)  // 99328

// trace constants: exp(-0.001/0.02), exp(+0.001/0.02), exp(-0.001/0.101)
#define DECAY_PM 0.95122942450071400f
#define INV_PM   1.05127109637602410f
#define DECAY_X  0.99014786313283800f
#define A_TRIPLET 0.0065f

#define NTRACE_BLK 256   // traces grid size == number of spike-count partials

// ============ static device scratch (no allocs; zero-initialized) ============
// pad cols [4112,4160) are NEVER written -> remain zero -> contribute 0 to GEMM
__device__ __half g_A[(size_t)P_DIM * K_COLS];  // [P,4160]: x_pre[t,b] | x_pre[T],b | 0-pad
__device__ __half g_B[(size_t)Q_DIM * K_COLS];  // [Q,4160]: fused B'     | bnd col   | 0-pad
__device__ unsigned int g_count_part[NTRACE_BLK];  // per-block spike counts (overwrite)

// ============ helpers ============
__device__ __forceinline__ uint32_t smem_u32(const void* p) {
    uint32_t a;
    asm("{ .reg .u64 t; cvta.to.shared.u64 t, %1; cvt.u32.u64 %0, t; }" : "=r"(a) : "l"(p));
    return a;
}
__device__ __forceinline__ uint32_t pack_h2(float lo, float hi) {
    __half2 h = __floats2half2_rn(lo, hi);
    return *reinterpret_cast<uint32_t*>(&h);
}

// ================= kernel 1: traces + fused operand packing =================
// 256 blocks x 256 threads; thread = one (b, n) sequence (recurrence serial in t).
// Pre side : A'[n, b*256+t] = x_pre[t];  A'[n, 4096+b] = x_pre[T]
// Post side: B'[n, b*256+t] = post*(Ap + c*x_trip) - Am*(x_post[t-1]/lam - x_post[t])
//            B'[n, 4096+b] = -Am * x_post[T-1] / lam
// (LTD folded into the x_pre contraction via summation by parts: pre[t] =
//  x_pre[t+1]/lam - x_pre[t], exact from the trace recurrence.)
__global__ void __launch_bounds__(256) traces_kernel(
    const float* __restrict__ pre,
    const float* __restrict__ post,
    const float* __restrict__ apP,
    const float* __restrict__ amP)
{
    __shared__ unsigned s_cnt[8];
    int idx = blockIdx.x * blockDim.x + threadIdx.x;   // 0..65535
    bool is_pre = idx < (NBATCH * P_DIM);
    int li = is_pre ? idx : idx - NBATCH * P_DIM;
    int n = li & (P_DIM - 1);
    int b = li >> 11;
    const float4* in4 = (const float4*)((is_pre ? pre : post) + ((size_t)(b * P_DIM + n) << 8));
    __half* o1 = (is_pre ? g_A : g_B) + (size_t)n * K_COLS + b * T_DIM;
    __half* ox = (is_pre ? g_A : g_B) + (size_t)n * K_COLS + K_EXTRA + b;
    unsigned cnt = 0;

    if (is_pre) {
        float x = 0.f;
        #pragma unroll 4
        for (int t8 = 0; t8 < T_DIM / 8; t8++) {
            float4 f0 = in4[2 * t8], f1 = in4[2 * t8 + 1];
            float fv[8] = {f0.x, f0.y, f0.z, f0.w, f1.x, f1.y, f1.z, f1.w};
            float xa[8];
            #pragma unroll
            for (int i = 0; i < 8; i++) {
                float s = fv[i];
                xa[i] = x;
                cnt += (s > 0.5f) ? 1u : 0u;
                x = DECAY_PM * (x + s);
            }
            uint4 ua;
            ua.x = pack_h2(xa[0], xa[1]); ua.y = pack_h2(xa[2], xa[3]);
            ua.z = pack_h2(xa[4], xa[5]); ua.w = pack_h2(xa[6], xa[7]);
            *(uint4*)(o1 + t8 * 8) = ua;          // x_pre trace
        }
        *ox = __float2half(x);                    // x_pre[T] boundary column
    } else {
        float Ap = *apP;
        float Am = *amP;
        float xm = 0.f, xt = 0.f, xm_prev = 0.f;
        #pragma unroll 4
        for (int t8 = 0; t8 < T_DIM / 8; t8++) {
            float4 f0 = in4[2 * t8], f1 = in4[2 * t8 + 1];
            float fv[8] = {f0.x, f0.y, f0.z, f0.w, f1.x, f1.y, f1.z, f1.w};
            float v[8];
            #pragma unroll
            for (int i = 0; i < 8; i++) {
                float s = fv[i];
                // fused column: ltp+triplet part minus ltd (summed-by-parts) part
                v[i] = s * (Ap + A_TRIPLET * xt) - Am * (xm_prev * INV_PM - xm);
                cnt += (s > 0.5f) ? 1u : 0u;
                xm_prev = xm;
                xm = DECAY_PM * (xm + s);
                xt = DECAY_X * (xt + s);
            }
            uint4 ua;
            ua.x = pack_h2(v[0], v[1]); ua.y = pack_h2(v[2], v[3]);
            ua.z = pack_h2(v[4], v[5]); ua.w = pack_h2(v[6], v[7]);
            *(uint4*)(o1 + t8 * 8) = ua;
        }
        // boundary: -Am * x_post[T-1] / lam   (xm_prev holds x_post[T-1])
        *ox = __float2half(-Am * xm_prev * INV_PM);
    }
    // deterministic spike-count: warp reduce -> block reduce -> overwrite slot
    #pragma unroll
    for (int o = 16; o; o >>= 1) cnt += __shfl_xor_sync(0xffffffffu, cnt, o);
    if ((threadIdx.x & 31) == 0) s_cnt[threadIdx.x >> 5] = cnt;
    __syncthreads();
    if (threadIdx.x == 0) {
        unsigned t = 0;
        #pragma unroll
        for (int i = 0; i < 8; i++) t += s_cnt[i];
        g_count_part[blockIdx.x] = t;
    }
}

// ================= mma.sync building blocks (sm_80-compatible PTX) =============
__device__ __forceinline__ void ldsm4(uint32_t& r0, uint32_t& r1, uint32_t& r2, uint32_t& r3,
                                      uint32_t addr) {
    asm volatile("ldmatrix.sync.aligned.m8n8.x4.shared.b16 {%0,%1,%2,%3}, [%4];"
                 : "=r"(r0), "=r"(r1), "=r"(r2), "=r"(r3) : "r"(addr));
}
__device__ __forceinline__ void mma16816(float* d, const uint32_t* a, uint32_t b0, uint32_t b1) {
    asm volatile(
        "mma.sync.aligned.m16n8k16.row.col.f32.f16.f16.f32 "
        "{%0,%1,%2,%3}, {%4,%5,%6,%7}, {%8,%9}, {%0,%1,%2,%3};"
        : "+f"(d[0]), "+f"(d[1]), "+f"(d[2]), "+f"(d[3])
        : "r"(a[0]), "r"(a[1]), "r"(a[2]), "r"(a[3]), "r"(b0), "r"(b1));
}
__device__ __forceinline__ void cpasync16(uint32_t dst, const void* src) {
    asm volatile("cp.async.cg.shared.global [%0], [%1], 16;" :: "r"(dst), "l"(src));
}

// ================= kernel 2: GEMM + fused epilogue =================
// grid (16,16) = 256 CTAs, 128 threads (warp grid 2x2, warp tile 64x64).
// D[p,q] = A'[p,:].B'[q,:]^T over K=4160;  out = clip(weights + D*scale, -2, 2)
__global__ void __launch_bounds__(128) stdp_gemm_kernel(
    const float* __restrict__ weights,
    float* __restrict__ out)
{
    extern __shared__ __align__(1024) char smem[];
    uint32_t sb = smem_u32(smem);
    int tid = threadIdx.x;
    int wid = tid >> 5, lane = tid & 31;
    int m0 = blockIdx.x * TILE_M;
    int q0 = blockIdx.y * TILE_N;

    int wm = (wid & 1) * 64;        // warp M offset
    int wn = (wid >> 1) * 64;       // warp N offset
    const __half* Ag = g_A;
    const __half* Bg = g_B;

    float acc[128];
    #pragma unroll
    for (int i = 0; i < 128; i++) acc[i] = 0.f;

    // stage loader: 128 threads x 16B, 8 iters per operand
    auto load_stage = [&](int s, int kbase) {
        uint32_t a_s = sb + SMEM_DATA0 + s * STAGE_BYTES;
        uint32_t b_s = a_s + A_TILE_BYTES;
        #pragma unroll
        for (int i = 0; i < 8; i++) {
            int id = i * 128 + tid;            // 0..1023
            int row = id >> 3, ch = id & 7;
            uint32_t so = (uint32_t)(row * 128 + ((ch ^ (row & 7)) << 4));
            cpasync16(a_s + so, Ag + (size_t)(m0 + row) * K_COLS + kbase + ch * 8);
            cpasync16(b_s + so, Bg + (size_t)(q0 + row) * K_COLS + kbase + ch * 8);
        }
    };

    load_stage(0, 0);
    asm volatile("cp.async.commit_group;" ::: "memory");
    load_stage(1, CHUNK_K);
    asm volatile("cp.async.commit_group;" ::: "memory");

    int s_cur = 0, s_nxt = 2;
    #pragma unroll 1
    for (int c = 0; c < NCHUNK; c++) {
        asm volatile("cp.async.wait_group 1;" ::: "memory");
        __syncthreads();
        if (c + 2 < NCHUNK) load_stage(s_nxt, (c + 2) * CHUNK_K);
        asm volatile("cp.async.commit_group;" ::: "memory");

        uint32_t a_s = sb + SMEM_DATA0 + s_cur * STAGE_BYTES;
        uint32_t b_s = a_s + A_TILE_BYTES;
        #pragma unroll
        for (int kk = 0; kk < 4; kk++) {
            uint32_t af[4][4], bf[4][4];
            #pragma unroll
            for (int mt = 0; mt < 4; mt++) {
                int m_r = wm + mt * 16 + (lane & 15);
                int kch = kk * 2 + (lane >> 4);
                ldsm4(af[mt][0], af[mt][1], af[mt][2], af[mt][3],
                      a_s + (uint32_t)(m_r * 128 + ((kch ^ (m_r & 7)) << 4)));
            }
            #pragma unroll
            for (int pr = 0; pr < 4; pr++) {
                int g = lane >> 3;
                int n_r = wn + pr * 16 + (lane & 7) + (g >> 1) * 8;
                int kch = kk * 2 + (g & 1);
                ldsm4(bf[pr][0], bf[pr][1], bf[pr][2], bf[pr][3],
                      b_s + (uint32_t)(n_r * 128 + ((kch ^ (n_r & 7)) << 4)));
            }
            #pragma unroll
            for (int mt = 0; mt < 4; mt++) {
                #pragma unroll
                for (int nt = 0; nt < 8; nt++) {
                    int pr = nt >> 1, off = (nt & 1) * 2;
                    mma16816(&acc[(mt * 8 + nt) * 4], af[mt], bf[pr][off], bf[pr][off + 1]);
                }
            }
        }
        s_cur = (s_cur + 1 == NSTAGE) ? 0 : s_cur + 1;
        s_nxt = (s_nxt + 1 == NSTAGE) ? 0 : s_nxt + 1;
    }

    // ---- spike-count reduction (partials written by traces_kernel) ----
    unsigned c2 = g_count_part[tid] + g_count_part[tid + 128];
    #pragma unroll
    for (int o = 16; o; o >>= 1) c2 += __shfl_xor_sync(0xffffffffu, c2, o);
    unsigned* sc = (unsigned*)(smem + 128);   // header region, never a cp.async target
    if (lane == 0) sc[wid] = c2;
    __syncthreads();
    float act = (float)(sc[0] + sc[1] + sc[2] + sc[3]) * (1.0f / (NBATCH * T_DIM));
    float scale = sqrtf(0.1f / (act + 1e-6f));

    // ---- fused epilogue ----
    #pragma unroll
    for (int mt = 0; mt < 4; mt++) {
        int r0 = m0 + wm + mt * 16 + (lane >> 2);
        #pragma unroll
        for (int nt = 0; nt < 8; nt++) {
            int cidx = q0 + wn + nt * 8 + (lane & 3) * 2;
            const float* d = &acc[(mt * 8 + nt) * 4];
            {
                const float2 w = *(const float2*)(weights + (size_t)r0 * Q_DIM + cidx);
                float2 o;
                o.x = fminf(fmaxf(fmaf(d[0], scale, w.x), -2.f), 2.f);
                o.y = fminf(fmaxf(fmaf(d[1], scale, w.y), -2.f), 2.f);
                *(float2*)(out + (size_t)r0 * Q_DIM + cidx) = o;
            }
            {
                const float2 w = *(const float2*)(weights + (size_t)(r0 + 8) * Q_DIM + cidx);
                float2 o;
                o.x = fminf(fmaxf(fmaf(d[2], scale, w.x), -2.f), 2.f);
                o.y = fminf(fmaxf(fmaf(d[3], scale, w.y), -2.f), 2.f);
                *(float2*)(out + (size_t)(r0 + 8) * Q_DIM + cidx) = o;
            }
        }
    }
}

// ================= host =================
extern "C" void kernel_launch(void* const* d_in, const int* in_sizes, int n_in,
                              void* d_out, int out_size)
{
    const float* pre  = (const float*)d_in[0];
    const float* post = (const float*)d_in[1];
    const float* w    = (const float*)d_in[2];
    const float* ap   = (const float*)d_in[3];
    const float* am   = (const float*)d_in[4];
    float* out = (float*)d_out;

    traces_kernel<<<NTRACE_BLK, 256>>>(pre, post, ap, am);

    cudaFuncSetAttribute(stdp_gemm_kernel, cudaFuncAttributeMaxDynamicSharedMemorySize,
                         SMEM_DYN_BYTES);
    dim3 grid(P_DIM / TILE_M, Q_DIM / TILE_N);   // (16, 16)
    stdp_gemm_kernel<<<grid, 128, SMEM_DYN_BYTES>>>(w, out);
}

// round 8
// speedup vs baseline: 2.6564x; 1.0478x over previous
#include <cuda_runtime.h>
#include <cuda.h>
#include <cuda_fp16.h>
#include <cstdint>

// ================= problem dims =================
#define P_DIM 2048
#define Q_DIM 2048
#define NBATCH 16
#define T_DIM 256
#define K_DATA 4096                 // (t,b) columns
#define K_EXTRA 4096                // start of boundary columns (16 of them)
#define K_COLS 4160                 // padded to 65 chunks of 64 (pad stays zero)

// ================= gemm config =================
#define TILE_M 128
#define TILE_N 128
#define CHUNK_K 64                  // halves per k-chunk = 128 bytes per row
#define NCHUNK (K_COLS / CHUNK_K)   // 65
#define NSTAGE 3
#define A_TILE_BYTES (TILE_M * 128) // 16384
#define B_TILE_BYTES (TILE_N * 128) // 16384
#define STAGE_BYTES (A_TILE_BYTES + B_TILE_BYTES)   // 32768
#define SMEM_DATA0 1024
#define SMEM_DYN_BYTES (SMEM_DATA0 + NSTAGE * STAGE_BYTES)  // 99328

// trace constants: exp(-0.001/0.02), exp(+0.001/0.02), exp(-0.001/0.101)
#define DECAY_PM 0.95122942450071400f
#define INV_PM   1.05127109637602410f
#define DECAY_X  0.99014786313283800f
#define A_TRIPLET 0.0065f

#define NTRACE_BLK 256   // traces grid size == number of spike-count partials

// ============ static device scratch (no allocs; zero-initialized) ============
// pad cols [4112,4160) are NEVER written -> remain zero -> contribute 0 to GEMM
__device__ __half g_A[(size_t)P_DIM * K_COLS];  // [P,4160]: x_pre[t,b] | x_pre[T],b | 0-pad
__device__ __half g_B[(size_t)Q_DIM * K_COLS];  // [Q,4160]: fused B'   | bnd col    | 0-pad
__device__ unsigned int g_count_part[NTRACE_BLK];  // per-block spike counts (overwrite)

// ============ helpers ============
__device__ __forceinline__ uint32_t smem_u32(const void* p) {
    uint32_t a;
    asm("{ .reg .u64 t; cvta.to.shared.u64 t, %1; cvt.u32.u64 %0, t; }" : "=r"(a) : "l"(p));
    return a;
}
__device__ __forceinline__ uint32_t pack_h2(float lo, float hi) {
    __half2 h = __floats2half2_rn(lo, hi);
    return *reinterpret_cast<uint32_t*>(&h);
}

// ================= kernel 1: traces + fused operand packing =================
// Pre side : A'[n, b*256+t] = x_pre[t];  A'[n, 4096+b] = x_pre[T]
// Post side: B'[n, b*256+t] = post*(Ap + c*x_trip) - Am*(x_post[t-1]/lam - x_post[t])
//            B'[n, 4096+b] = -Am * x_post[T-1] / lam
// (LTD folded into the x_pre contraction via summation by parts: pre[t] =
//  x_pre[t+1]/lam - x_pre[t], exact from the trace recurrence.)
__global__ void __launch_bounds__(256) traces_kernel(
    const float* __restrict__ pre,
    const float* __restrict__ post,
    const float* __restrict__ apP,
    const float* __restrict__ amP)
{
    __shared__ unsigned s_cnt[8];
    int idx = blockIdx.x * blockDim.x + threadIdx.x;   // 0..65535
    bool is_pre = idx < (NBATCH * P_DIM);
    int li = is_pre ? idx : idx - NBATCH * P_DIM;
    int n = li & (P_DIM - 1);
    int b = li >> 11;
    const float4* in4 = (const float4*)((is_pre ? pre : post) + ((size_t)(b * P_DIM + n) << 8));
    __half* o1 = (is_pre ? g_A : g_B) + (size_t)n * K_COLS + b * T_DIM;
    __half* ox = (is_pre ? g_A : g_B) + (size_t)n * K_COLS + K_EXTRA + b;
    unsigned cnt = 0;

    if (is_pre) {
        float x = 0.f;
        #pragma unroll 4
        for (int t8 = 0; t8 < T_DIM / 8; t8++) {
            float4 f0 = in4[2 * t8], f1 = in4[2 * t8 + 1];
            float fv[8] = {f0.x, f0.y, f0.z, f0.w, f1.x, f1.y, f1.z, f1.w};
            float xa[8];
            #pragma unroll
            for (int i = 0; i < 8; i++) {
                float s = fv[i];
                xa[i] = x;
                cnt += (s > 0.5f) ? 1u : 0u;
                x = DECAY_PM * (x + s);
            }
            uint4 ua;
            ua.x = pack_h2(xa[0], xa[1]); ua.y = pack_h2(xa[2], xa[3]);
            ua.z = pack_h2(xa[4], xa[5]); ua.w = pack_h2(xa[6], xa[7]);
            *(uint4*)(o1 + t8 * 8) = ua;          // x_pre trace
        }
        *ox = __float2half(x);                    // x_pre[T] boundary column
    } else {
        float Ap = *apP;
        float Am = *amP;
        float xm = 0.f, xt = 0.f, xm_prev = 0.f;
        #pragma unroll 4
        for (int t8 = 0; t8 < T_DIM / 8; t8++) {
            float4 f0 = in4[2 * t8], f1 = in4[2 * t8 + 1];
            float fv[8] = {f0.x, f0.y, f0.z, f0.w, f1.x, f1.y, f1.z, f1.w};
            float v[8];
            #pragma unroll
            for (int i = 0; i < 8; i++) {
                float s = fv[i];
                v[i] = s * (Ap + A_TRIPLET * xt) - Am * (xm_prev * INV_PM - xm);
                cnt += (s > 0.5f) ? 1u : 0u;
                xm_prev = xm;
                xm = DECAY_PM * (xm + s);
                xt = DECAY_X * (xt + s);
            }
            uint4 ua;
            ua.x = pack_h2(v[0], v[1]); ua.y = pack_h2(v[2], v[3]);
            ua.z = pack_h2(v[4], v[5]); ua.w = pack_h2(v[6], v[7]);
            *(uint4*)(o1 + t8 * 8) = ua;
        }
        *ox = __float2half(-Am * xm_prev * INV_PM);   // -Am*x_post[T-1]/lam
    }
    // deterministic spike-count: warp reduce -> block reduce -> overwrite slot
    #pragma unroll
    for (int o = 16; o; o >>= 1) cnt += __shfl_xor_sync(0xffffffffu, cnt, o);
    if ((threadIdx.x & 31) == 0) s_cnt[threadIdx.x >> 5] = cnt;
    __syncthreads();
    if (threadIdx.x == 0) {
        unsigned t = 0;
        #pragma unroll
        for (int i = 0; i < 8; i++) t += s_cnt[i];
        g_count_part[blockIdx.x] = t;
    }
}

// ================= mma.sync building blocks (sm_80-compatible PTX) =============
__device__ __forceinline__ void ldsm4(uint32_t& r0, uint32_t& r1, uint32_t& r2, uint32_t& r3,
                                      uint32_t addr) {
    asm volatile("ldmatrix.sync.aligned.m8n8.x4.shared.b16 {%0,%1,%2,%3}, [%4];"
                 : "=r"(r0), "=r"(r1), "=r"(r2), "=r"(r3) : "r"(addr));
}
__device__ __forceinline__ void mma16816(float* d, const uint32_t* a, uint32_t b0, uint32_t b1) {
    asm volatile(
        "mma.sync.aligned.m16n8k16.row.col.f32.f16.f16.f32 "
        "{%0,%1,%2,%3}, {%4,%5,%6,%7}, {%8,%9}, {%0,%1,%2,%3};"
        : "+f"(d[0]), "+f"(d[1]), "+f"(d[2]), "+f"(d[3])
        : "r"(a[0]), "r"(a[1]), "r"(a[2]), "r"(a[3]), "r"(b0), "r"(b1));
}
__device__ __forceinline__ void cpasync16(uint32_t dst, const void* src) {
    asm volatile("cp.async.cg.shared.global [%0], [%1], 16;" :: "r"(dst), "l"(src));
}

// ================= kernel 2: GEMM + fused epilogue =================
// grid (16,16) = 256 CTAs, 128 threads (warp grid 2x2, warp tile 64x64).
// Fragments double-buffered across kk: ldsm for kk+1 overlaps mma of kk.
__global__ void __launch_bounds__(128) stdp_gemm_kernel(
    const float* __restrict__ weights,
    float* __restrict__ out)
{
    extern __shared__ __align__(1024) char smem[];
    uint32_t sb = smem_u32(smem);
    int tid = threadIdx.x;
    int wid = tid >> 5, lane = tid & 31;
    int m0 = blockIdx.x * TILE_M;
    int q0 = blockIdx.y * TILE_N;

    int wm = (wid & 1) * 64;        // warp M offset
    int wn = (wid >> 1) * 64;       // warp N offset
    const __half* Ag = g_A;
    const __half* Bg = g_B;

    float acc[128];
    #pragma unroll
    for (int i = 0; i < 128; i++) acc[i] = 0.f;

    // precomputed per-thread ldsm byte offsets (swizzled), relative to tile base
    uint32_t a_off[4], b_off[4];
    {
        #pragma unroll
        for (int mt = 0; mt < 4; mt++) {
            int m_r = wm + mt * 16 + (lane & 15);
            int kch = lane >> 4;
            a_off[mt] = (uint32_t)(m_r * 128 + ((kch ^ (m_r & 7)) << 4));
        }
        int g = lane >> 3;
        #pragma unroll
        for (int pr = 0; pr < 4; pr++) {
            int n_r = wn + pr * 16 + (lane & 7) + (g >> 1) * 8;
            int kch = g & 1;
            b_off[pr] = (uint32_t)(n_r * 128 + ((kch ^ (n_r & 7)) << 4));
        }
    }
    // kch advances by +2 per kk; swizzle XOR bits are [6:4] of addr, kch sits at
    // bits [4..]; row-dependent XOR is constant per thread, so +kk*2*16 bytes is
    // NOT swizzle-safe in general... but note: kch^row XOR only affects bits[6:4],
    // and kch*16 for kch in {0..7} occupies exactly bits [4:6]. (a^r) for a+2:
    // ((kch+2)^r)<<4 != ((kch^r)<<4)+32 when carry interacts. So recompute via XOR:
    // addr(kk) = base_addr_xor ^ (((kk*2) ^ 0) <<4)? Since XOR with r is bitwise,
    // ((kch0 + 2k) ^ r) is not (kch0^r) + 2k. We instead XOR the *data chunk index*:
    // for kch in 0..7, addr = row*128 + ((kch ^ (row&7))<<4). Define base with kch0,
    // then addr_k = row*128 + (((kch0 + 2k) & 7 ^ row&7) << 4). kch0 + 2k < 8 always
    // (kch0 in {0,1} + 2k, k<=3 -> max 7), no carry past bit 2 of kch, and XOR with
    // row affects the same 3 bits: addr_k = (base & ~0x70) | ((((base>>4)&7) ^ (2k)) << 4)
    // because ( (kch0^r) ^ 2k ) == ( (kch0 + 2k) ^ r ) when kch0 in {0,1} and 2k has
    // bit0 clear (no overlap with kch0's bit0 -> addition == XOR). Valid here.

    auto load_stage = [&](int s, int kbase) {
        uint32_t a_s = sb + SMEM_DATA0 + s * STAGE_BYTES;
        uint32_t b_s = a_s + A_TILE_BYTES;
        #pragma unroll
        for (int i = 0; i < 8; i++) {
            int id = i * 128 + tid;            // 0..1023
            int row = id >> 3, ch = id & 7;
            uint32_t so = (uint32_t)(row * 128 + ((ch ^ (row & 7)) << 4));
            cpasync16(a_s + so, Ag + (size_t)(m0 + row) * K_COLS + kbase + ch * 8);
            cpasync16(b_s + so, Bg + (size_t)(q0 + row) * K_COLS + kbase + ch * 8);
        }
    };

    load_stage(0, 0);
    asm volatile("cp.async.commit_group;" ::: "memory");
    load_stage(1, CHUNK_K);
    asm volatile("cp.async.commit_group;" ::: "memory");

    uint32_t af[2][4][4], bf[2][4][4];

    // fragment loader for one kk into buffer fb (XOR trick for kch advance)
    #define LOAD_FRAGS(fb, a_s, b_s, kk)                                          \
        do {                                                                      \
            uint32_t kx = (uint32_t)((kk) * 2) << 4;                              \
            _Pragma("unroll")                                                     \
            for (int mt = 0; mt < 4; mt++)                                        \
                ldsm4(af[fb][mt][0], af[fb][mt][1], af[fb][mt][2], af[fb][mt][3], \
                      (a_s) + (a_off[mt] ^ kx));                                  \
            _Pragma("unroll")                                                     \
            for (int pr = 0; pr < 4; pr++)                                        \
                ldsm4(bf[fb][pr][0], bf[fb][pr][1], bf[fb][pr][2], bf[fb][pr][3], \
                      (b_s) + (b_off[pr] ^ kx));                                  \
        } while (0)

    int s_cur = 0, s_nxt = 2;
    #pragma unroll 1
    for (int c = 0; c < NCHUNK; c++) {
        asm volatile("cp.async.wait_group 1;" ::: "memory");
        __syncthreads();
        if (c + 2 < NCHUNK) load_stage(s_nxt, (c + 2) * CHUNK_K);
        asm volatile("cp.async.commit_group;" ::: "memory");

        uint32_t a_s = sb + SMEM_DATA0 + s_cur * STAGE_BYTES;
        uint32_t b_s = a_s + A_TILE_BYTES;

        LOAD_FRAGS(0, a_s, b_s, 0);
        #pragma unroll
        for (int kk = 0; kk < 4; kk++) {
            int cur = kk & 1;
            if (kk < 3) LOAD_FRAGS((kk + 1) & 1, a_s, b_s, kk + 1);
            #pragma unroll
            for (int mt = 0; mt < 4; mt++) {
                #pragma unroll
                for (int nt = 0; nt < 8; nt++) {
                    int pr = nt >> 1, off = (nt & 1) * 2;
                    mma16816(&acc[(mt * 8 + nt) * 4], af[cur][mt],
                             bf[cur][pr][off], bf[cur][pr][off + 1]);
                }
            }
        }
        s_cur = (s_cur + 1 == NSTAGE) ? 0 : s_cur + 1;
        s_nxt = (s_nxt + 1 == NSTAGE) ? 0 : s_nxt + 1;
    }
    #undef LOAD_FRAGS

    // ---- spike-count reduction (partials written by traces_kernel) ----
    unsigned c2 = g_count_part[tid] + g_count_part[tid + 128];
    #pragma unroll
    for (int o = 16; o; o >>= 1) c2 += __shfl_xor_sync(0xffffffffu, c2, o);
    unsigned* sc = (unsigned*)(smem + 128);   // header region, never a cp.async target
    if (lane == 0) sc[wid] = c2;
    __syncthreads();
    float act = (float)(sc[0] + sc[1] + sc[2] + sc[3]) * (1.0f / (NBATCH * T_DIM));
    float scale = sqrtf(0.1f / (act + 1e-6f));

    // ---- fused epilogue ----
    #pragma unroll
    for (int mt = 0; mt < 4; mt++) {
        int r0 = m0 + wm + mt * 16 + (lane >> 2);
        #pragma unroll
        for (int nt = 0; nt < 8; nt++) {
            int cidx = q0 + wn + nt * 8 + (lane & 3) * 2;
            const float* d = &acc[(mt * 8 + nt) * 4];
            {
                const float2 w = *(const float2*)(weights + (size_t)r0 * Q_DIM + cidx);
                float2 o;
                o.x = fminf(fmaxf(fmaf(d[0], scale, w.x), -2.f), 2.f);
                o.y = fminf(fmaxf(fmaf(d[1], scale, w.y), -2.f), 2.f);
                *(float2*)(out + (size_t)r0 * Q_DIM + cidx) = o;
            }
            {
                const float2 w = *(const float2*)(weights + (size_t)(r0 + 8) * Q_DIM + cidx);
                float2 o;
                o.x = fminf(fmaxf(fmaf(d[2], scale, w.x), -2.f), 2.f);
                o.y = fminf(fmaxf(fmaf(d[3], scale, w.y), -2.f), 2.f);
                *(float2*)(out + (size_t)(r0 + 8) * Q_DIM + cidx) = o;
            }
        }
    }
}

// ================= host =================
extern "C" void kernel_launch(void* const* d_in, const int* in_sizes, int n_in,
                              void* d_out, int out_size)
{
    const float* pre  = (const float*)d_in[0];
    const float* post = (const float*)d_in[1];
    const float* w    = (const float*)d_in[2];
    const float* ap   = (const float*)d_in[3];
    const float* am   = (const float*)d_in[4];
    float* out = (float*)d_out;

    traces_kernel<<<NTRACE_BLK, 256>>>(pre, post, ap, am);

    cudaFuncSetAttribute(stdp_gemm_kernel, cudaFuncAttributeMaxDynamicSharedMemorySize,
                         SMEM_DYN_BYTES);
    dim3 grid(P_DIM / TILE_M, Q_DIM / TILE_N);   // (16, 16)
    stdp_gemm_kernel<<<grid, 128, SMEM_DYN_BYTES>>>(w, out);
}